// round 15
// baseline (speedup 1.0000x reference)
#include <cuda_runtime.h>
#include <cstdint>

#define B     64
#define H     1024
#define KC    32          // k per chunk
#define NTL   256         // threads per CTA (2 warpgroups of 128)
#define NB    128         // persistent CTAs (single wave on 148+ SMs)

typedef unsigned long long u64;

// ---------------- device-global state (no cudaMalloc allowed) ----------------
__device__ float g_Wp[4096 * 1024];        // W' = W_ih0 @ out_w   (16 MB)
__device__ float g_bias[3][4096];          // [0]=l0 (t>0), [1]=l0 (t=0), [2]=l1
__device__ float g_h0[2][B * H];
__device__ float g_c0[2][B * H];
__device__ float g_h1[2][B * H];
__device__ float g_c1[2][B * H];
__device__ unsigned g_bar_cnt;
__device__ unsigned g_bar_gen;

// ---------------- helpers ----------------
__device__ __forceinline__ u64 ffma2(u64 a, u64 b, u64 c) {
    u64 d;
    asm("fma.rn.f32x2 %0, %1, %2, %3;" : "=l"(d) : "l"(a), "l"(b), "l"(c));
    return d;
}
__device__ __forceinline__ float lo32f(u64 v) { return __uint_as_float((unsigned)(v & 0xffffffffULL)); }
__device__ __forceinline__ float hi32f(u64 v) { return __uint_as_float((unsigned)(v >> 32)); }
__device__ __forceinline__ float sigf(float x) { return 1.0f / (1.0f + expf(-x)); }

// ---------------- prep kernels ----------------
__global__ void prep_state(const float* __restrict__ h0, const float* __restrict__ c0) {
    int i = blockIdx.x * blockDim.x + threadIdx.x;
    if (i < B * H) {
        g_h0[0][i] = h0[i];
        g_c0[0][i] = c0[i];
        g_h1[0][i] = h0[B * H + i];
        g_c1[0][i] = c0[B * H + i];
    }
    if (blockIdx.x == 0 && threadIdx.x == 0) { g_bar_cnt = 0; g_bar_gen = 0; }
}

// bias folds: [0] = bih0+bhh0+Wih0@ob ; [1] = bih0+bhh0 ; [2] = bih1+bhh1
__global__ void prep_bias(const float* __restrict__ wih, const float* __restrict__ bih,
                          const float* __restrict__ bhh, const float* __restrict__ ob) {
    int gwarp = (blockIdx.x * blockDim.x + threadIdx.x) >> 5;
    int lane  = threadIdx.x & 31;
    int nwarps = (gridDim.x * blockDim.x) >> 5;
    for (int r = gwarp; r < 4096; r += nwarps) {
        float s = 0.0f;
        const float* wr = wih + (size_t)r * H;
        for (int m = lane; m < H; m += 32) s += wr[m] * ob[m];
        #pragma unroll
        for (int o = 16; o > 0; o >>= 1) s += __shfl_xor_sync(0xffffffffu, s, o);
        if (lane == 0) {
            float base = bih[r] + bhh[r];
            g_bias[0][r] = base + s;
            g_bias[1][r] = base;
            g_bias[2][r] = bih[4096 + r] + bhh[4096 + r];
        }
    }
}

// W'[n][k] = sum_m Wih0[n][m] * Ow[m][k]
__global__ void prep_wprime(const float* __restrict__ wih, const float* __restrict__ ow) {
    __shared__ float Aw[32][33];
    __shared__ float Bw[32][33];
    int tid = threadIdx.x;
    int k0 = blockIdx.x * 32, n0 = blockIdx.y * 32;
    int tx = tid & 15, ty = tid >> 4;
    float a00 = 0, a01 = 0, a10 = 0, a11 = 0;
    for (int mb = 0; mb < H; mb += 32) {
        __syncthreads();
        #pragma unroll
        for (int q = 0; q < 4; ++q) {
            int i = tid + q * 256;
            int r = i >> 5, c = i & 31;
            Aw[r][c] = wih[(size_t)(n0 + r) * H + mb + c];
            Bw[r][c] = ow[(size_t)(mb + r) * H + k0 + c];
        }
        __syncthreads();
        #pragma unroll 8
        for (int m = 0; m < 32; ++m) {
            float x0 = Aw[2 * ty][m], x1 = Aw[2 * ty + 1][m];
            float y0 = Bw[m][2 * tx], y1 = Bw[m][2 * tx + 1];
            a00 += x0 * y0; a01 += x0 * y1; a10 += x1 * y0; a11 += x1 * y1;
        }
    }
    int n = n0 + 2 * ty, k = k0 + 2 * tx;
    g_Wp[(size_t)n * H + k]           = a00;
    g_Wp[(size_t)n * H + k + 1]       = a01;
    g_Wp[(size_t)(n + 1) * H + k]     = a10;
    g_Wp[(size_t)(n + 1) * H + k + 1] = a11;
}

// ---------------- grid barrier (sense via generation counter) ----------------
__device__ __forceinline__ void grid_bar(unsigned gen) {
    __syncthreads();
    if (threadIdx.x == 0) {
        __threadfence();
        unsigned old = atomicAdd(&g_bar_cnt, 1u);
        if (old == NB - 1) {
            g_bar_cnt = 0;
            __threadfence();
            atomicExch(&g_bar_gen, gen);
        } else {
            unsigned v;
            do {
                asm volatile("ld.global.acquire.gpu.u32 %0, [%1];"
                             : "=r"(v) : "l"(&g_bar_gen));
                if (v < gen) __nanosleep(64);
            } while (v < gen);
        }
    }
    __syncthreads();
}

// ---------------- one LSTM layer phase (device, called per step) -------------
// CTA: 8 cells (cb..cb+7) x 4 gates = 32 gate cols, all 64 batch rows.
// Warpgroup 0 (tid<128): X-phase GEMM; warpgroup 1: H-phase GEMM. Split-K combine.
struct Smem {
    float2 As2[2][KC][33];
    float2 Ws2[2][KC][33];
    float  Gs[B][33];
};

__device__ __forceinline__ void lstm_phase(
    Smem* sm, int cb,
    const float* __restrict__ X,   const float* __restrict__ Hs,
    const float* __restrict__ Cin, float* __restrict__ Hout,
    float* __restrict__ Cout,      const float* __restrict__ Wx,
    const float* __restrict__ Wh,  const float* __restrict__ bias,
    float* __restrict__ Yout,      int has_x)
{
    int tid = threadIdx.x;
    int g = tid >> 7;              // warpgroup: 0 = X, 1 = H
    int tg = tid & 127;
    int gcq = tg & 7;              // cell within block (compute role)
    int bpg = tg >> 3;             // 16 groups of 2 batch-pairs
    int lb = tg >> 5, lk = tg & 31;

    const float* A = g ? Hs : X;
    const float* W = g ? Wh : Wx;
    int zeroA = (!has_x) && (g == 0);

    float* As2f  = (float*)sm->As2[g];     // row k at float idx k*66; float idx==batch row
    float2* Ws2p = (float2*)sm->Ws2[g];
    int sAbase = lk * 66 + lb;             // + q*4
    int sWbase = lk * 33 + lb;             // float2 idx, + q*4

    u64 acc[2][4];
    #pragma unroll
    for (int i = 0; i < 2; ++i)
        #pragma unroll
        for (int j = 0; j < 4; ++j) acc[i][j] = 0ULL;

    float ra[16], rw[8];
    // prefetch chunk 0
    {
        #pragma unroll
        for (int q = 0; q < 16; ++q)
            ra[q] = zeroA ? 0.0f : __ldcg(&A[(size_t)(q * 4 + lb) * H + lk]);
        #pragma unroll
        for (int q = 0; q < 8; ++q) {
            int gc = q * 4 + lb;
            int row = ((gc >> 3) << 10) + cb + (gc & 7);
            rw[q] = zeroA ? 0.0f : __ldg(&W[(size_t)row * H + lk]);
        }
    }

    for (int c = 0; c < 32; ++c) {
        __syncthreads();
        #pragma unroll
        for (int q = 0; q < 16; ++q) As2f[sAbase + q * 4] = ra[q];
        #pragma unroll
        for (int q = 0; q < 8; ++q) {
            float w = rw[q];
            Ws2p[sWbase + q * 4] = make_float2(w, w);
        }
        __syncthreads();
        if (c < 31) {
            int kb = (c + 1) << 5;
            #pragma unroll
            for (int q = 0; q < 16; ++q)
                ra[q] = zeroA ? 0.0f : __ldcg(&A[(size_t)(q * 4 + lb) * H + kb + lk]);
            #pragma unroll
            for (int q = 0; q < 8; ++q) {
                int gc = q * 4 + lb;
                int row = ((gc >> 3) << 10) + cb + (gc & 7);
                rw[q] = zeroA ? 0.0f : __ldg(&W[(size_t)row * H + kb + lk]);
            }
        }
        const u64* As = (const u64*)sm->As2[g];
        const u64* Ws = (const u64*)sm->Ws2[g];
        #pragma unroll 8
        for (int k = 0; k < KC; ++k) {
            u64 a0 = As[k * 33 + 2 * bpg];
            u64 a1 = As[k * 33 + 2 * bpg + 1];
            u64 w0 = Ws[k * 33 + gcq];           // gc = 8*gate + cell
            u64 w1 = Ws[k * 33 + 8 + gcq];
            u64 w2 = Ws[k * 33 + 16 + gcq];
            u64 w3 = Ws[k * 33 + 24 + gcq];
            acc[0][0] = ffma2(a0, w0, acc[0][0]);
            acc[0][1] = ffma2(a0, w1, acc[0][1]);
            acc[0][2] = ffma2(a0, w2, acc[0][2]);
            acc[0][3] = ffma2(a0, w3, acc[0][3]);
            acc[1][0] = ffma2(a1, w0, acc[1][0]);
            acc[1][1] = ffma2(a1, w1, acc[1][1]);
            acc[1][2] = ffma2(a1, w2, acc[1][2]);
            acc[1][3] = ffma2(a1, w3, acc[1][3]);
        }
    }

    // combine split-K partials + bias in Gs
    __syncthreads();
    if (g == 0) {
        #pragma unroll
        for (int i = 0; i < 2; ++i) {
            int b0 = 4 * bpg + 2 * i;
            #pragma unroll
            for (int j = 0; j < 4; ++j) {
                int gc = 8 * j + gcq;
                u64 a = acc[i][j];
                sm->Gs[b0][gc]     = lo32f(a);
                sm->Gs[b0 + 1][gc] = hi32f(a);
            }
        }
    }
    __syncthreads();
    if (g == 1) {
        #pragma unroll
        for (int i = 0; i < 2; ++i) {
            int b0 = 4 * bpg + 2 * i;
            #pragma unroll
            for (int j = 0; j < 4; ++j) {
                int gc = 8 * j + gcq;
                float bb = bias[(j << 10) + cb + gcq];
                u64 a = acc[i][j];
                sm->Gs[b0][gc]     += lo32f(a) + bb;
                sm->Gs[b0 + 1][gc] += hi32f(a) + bb;
            }
        }
    }
    __syncthreads();

    // cell update: 512 (b, cell) pairs, 2 per thread
    #pragma unroll
    for (int e = tid; e < B * 8; e += NTL) {
        int b = e >> 3, j = e & 7;
        float gi = sm->Gs[b][j];
        float gf = sm->Gs[b][8 + j];
        float gg = sm->Gs[b][16 + j];
        float go = sm->Gs[b][24 + j];
        int col = cb + j;
        float cold = __ldcg(&Cin[b * H + col]);
        float cn = sigf(gf) * cold + sigf(gi) * tanhf(gg);
        float hn = sigf(go) * tanhf(cn);
        Cout[b * H + col] = cn;
        Hout[b * H + col] = hn;
        if (Yout) Yout[b * H + col] = hn;
    }
}

// ---------------- persistent sequence kernel ----------------
__global__ __launch_bounds__(NTL, 1) void lstm_seq(
    const float* __restrict__ wih1, const float* __restrict__ whh0,
    const float* __restrict__ whh1, float* __restrict__ out, int T)
{
    __shared__ Smem sm;
    int cb = blockIdx.x * 8;
    unsigned gen = 0;

    for (int t = 0; t < T; ++t) {
        int rb = t & 1, wb = rb ^ 1;
        // layer 0 (out-projection folded into g_Wp; x_t = h1_{t-1})
        lstm_phase(&sm, cb,
                   g_h1[rb], g_h0[rb], g_c0[rb], g_h0[wb], g_c0[wb],
                   g_Wp, whh0, g_bias[t ? 0 : 1], nullptr, t > 0);
        grid_bar(++gen);
        // layer 1
        lstm_phase(&sm, cb,
                   g_h0[wb], g_h1[rb], g_c1[rb], g_h1[wb], g_c1[wb],
                   wih1, whh1, g_bias[2], out + (size_t)t * B * H, 1);
        grid_bar(++gen);
    }
}

// ---------------- launch ----------------
extern "C" void kernel_launch(void* const* d_in, const int* in_sizes, int n_in,
                              void* d_out, int out_size) {
    const float* h0  = (const float*)d_in[0];
    const float* c0v = (const float*)d_in[1];
    const float* wih = (const float*)d_in[2];
    const float* whh = (const float*)d_in[3];
    const float* bih = (const float*)d_in[4];
    const float* bhh = (const float*)d_in[5];
    const float* ow  = (const float*)d_in[6];
    const float* ob  = (const float*)d_in[7];
    float* out = (float*)d_out;
    int T = out_size / (B * H);

    prep_state<<<256, 256>>>(h0, c0v);
    prep_bias<<<128, 256>>>(wih, bih, bhh, ob);
    prep_wprime<<<dim3(32, 128), 256>>>(wih, ow);

    const float* wih1 = wih + (size_t)4096 * 1024;
    const float* whh0 = whh;
    const float* whh1 = whh + (size_t)4096 * 1024;

    lstm_seq<<<NB, NTL>>>(wih1, whh0, whh1, out, T);
}

// round 16
// speedup vs baseline: 1.7192x; 1.7192x over previous
#include <cuda_runtime.h>
#include <cstdint>

#define B_    64
#define H_    1024
#define NB    128          // persistent CTAs
#define NT    256          // threads per CTA
#define KC    32           // k per chunk
#define NCH   16           // chunks per phase (per-group k = 512)

typedef unsigned long long u64;

// ---------------- smem layout (bytes) ----------------
#define ACT_ROW 272                    // 64 floats + 16B pad
#define ACT_GSZ (KC * ACT_ROW)         // 8704
#define OFF_ACT 0                      // [2 buf][4 g][KC][ACT_ROW] = 69632
#define W_ROW   144                    // 16 u64 pairs + 16B pad
#define W_GSZ   (KC * W_ROW)           // 4608
#define OFF_W   69632                  // [2][4][KC][W_ROW] = 36864
#define OFF_GS  106496                 // [4][64][17] u64 = 34816
#define GS_ROW  17
#define OFF_BIAS 141312                // 3*32 floats
#define SMEM_TOT 141696

// ---------------- device globals (no cudaMalloc) ----------------
__device__ __align__(256) float g_Wp[4096 * 1024];            // W' = W_ih0 @ out_w
__device__ __align__(256) u64   g_Wpair[(size_t)4 * 128 * 1024 * 16]; // paired per-CTA weights
__device__ float g_bias[3][4096];
__device__ __align__(256) float g_h0T[2][H_ * B_];            // transposed [col][b]
__device__ __align__(256) float g_h1T[2][H_ * B_];
__device__ unsigned g_bar_cnt;
__device__ unsigned g_bar_gen;

// ---------------- helpers ----------------
__device__ __forceinline__ u64 ffma2(u64 a, u64 b, u64 c) {
    u64 d;
    asm("fma.rn.f32x2 %0, %1, %2, %3;" : "=l"(d) : "l"(a), "l"(b), "l"(c));
    return d;
}
__device__ __forceinline__ u64 splat2(float f) {
    u64 r;
    asm("mov.b64 %0, {%1, %1};" : "=l"(r) : "f"(f));
    return r;
}
__device__ __forceinline__ void cpasync16(uint32_t dst, const void* src) {
    asm volatile("cp.async.cg.shared.global [%0], [%1], 16;"
                 :: "r"(dst), "l"(__cvta_generic_to_global(src)) : "memory");
}
__device__ __forceinline__ float sigf(float x) { return 1.0f / (1.0f + __expf(-x)); }
__device__ __forceinline__ float tanhf_(float x) { return 2.0f / (1.0f + __expf(-2.0f * x)) - 1.0f; }

// ---------------- prep kernels ----------------
__global__ void prep_state(const float* __restrict__ h0) {
    int i = blockIdx.x * blockDim.x + threadIdx.x;   // 65536 threads
    if (i < B_ * H_) {
        int b = i >> 10, col = i & 1023;
        g_h0T[0][col * B_ + b] = h0[i];
        g_h1T[0][col * B_ + b] = h0[B_ * H_ + i];
    }
    if (i == 0) { g_bar_cnt = 0; g_bar_gen = 0; }
}

// bias folds: [0] = bih0+bhh0+Wih0@ob ; [1] = bih0+bhh0 ; [2] = bih1+bhh1
__global__ void prep_bias(const float* __restrict__ wih, const float* __restrict__ bih,
                          const float* __restrict__ bhh, const float* __restrict__ ob) {
    int gwarp = (blockIdx.x * blockDim.x + threadIdx.x) >> 5;
    int lane  = threadIdx.x & 31;
    int nwarps = (gridDim.x * blockDim.x) >> 5;
    for (int r = gwarp; r < 4096; r += nwarps) {
        float s = 0.0f;
        const float* wr = wih + (size_t)r * H_;
        for (int m = lane; m < H_; m += 32) s += wr[m] * ob[m];
        #pragma unroll
        for (int o = 16; o > 0; o >>= 1) s += __shfl_xor_sync(0xffffffffu, s, o);
        if (lane == 0) {
            float base = bih[r] + bhh[r];
            g_bias[0][r] = base + s;
            g_bias[1][r] = base;
            g_bias[2][r] = bih[4096 + r] + bhh[4096 + r];
        }
    }
}

// W'[n][k] = sum_m Wih0[n][m] * Ow[m][k]
__global__ void prep_wprime(const float* __restrict__ wih, const float* __restrict__ ow) {
    __shared__ float Aw[32][33];
    __shared__ float Bw[32][33];
    int tid = threadIdx.x;
    int k0 = blockIdx.x * 32, n0 = blockIdx.y * 32;
    int tx = tid & 15, ty = tid >> 4;
    float a00 = 0, a01 = 0, a10 = 0, a11 = 0;
    for (int mb = 0; mb < H_; mb += 32) {
        __syncthreads();
        #pragma unroll
        for (int q = 0; q < 4; ++q) {
            int i = tid + q * 256;
            int r = i >> 5, c = i & 31;
            Aw[r][c] = wih[(size_t)(n0 + r) * H_ + mb + c];
            Bw[r][c] = ow[(size_t)(mb + r) * H_ + k0 + c];
        }
        __syncthreads();
        #pragma unroll 8
        for (int m = 0; m < 32; ++m) {
            float x0 = Aw[2 * ty][m], x1 = Aw[2 * ty + 1][m];
            float y0 = Bw[m][2 * tx], y1 = Bw[m][2 * tx + 1];
            a00 += x0 * y0; a01 += x0 * y1; a10 += x1 * y0; a11 += x1 * y1;
        }
    }
    int n = n0 + 2 * ty, k = k0 + 2 * tx;
    g_Wp[(size_t)n * H_ + k]            = a00;
    g_Wp[(size_t)n * H_ + k + 1]        = a01;
    g_Wp[(size_t)(n + 1) * H_ + k]      = a10;
    g_Wp[(size_t)(n + 1) * H_ + k + 1]  = a11;
}

// paired, per-CTA-tiled weights: g_Wpair[(m*128+cta)<<14 | k*16 + p] = (W[j0][k], W[j1][k]),
// j = 2p(+1) with permuted column j = gate*8 + cell, row = gate*1024 + cta*8 + cell
__global__ void prep_pair(const float* __restrict__ wih, const float* __restrict__ whh) {
    int cta = blockIdx.x, m = blockIdx.y, tid = threadIdx.x;
    const float* src;
    if (m == 0)      src = g_Wp;
    else if (m == 1) src = whh;
    else if (m == 2) src = wih + (size_t)4096 * 1024;
    else             src = whh + (size_t)4096 * 1024;
    u64* dstb = g_Wpair + ((size_t)(m * 128 + cta) << 14);
    for (int k = tid; k < 1024; k += 256) {
        #pragma unroll
        for (int p = 0; p < 16; ++p) {
            int j0 = 2 * p, j1 = 2 * p + 1;
            int r0 = ((j0 >> 3) << 10) + cta * 8 + (j0 & 7);
            int r1 = ((j1 >> 3) << 10) + cta * 8 + (j1 & 7);
            float lo = src[(size_t)r0 * H_ + k];
            float hi = src[(size_t)r1 * H_ + k];
            dstb[(size_t)k * 16 + p] =
                ((u64)__float_as_uint(hi) << 32) | (u64)__float_as_uint(lo);
        }
    }
}

// ---------------- grid barrier ----------------
__device__ __forceinline__ void grid_bar(unsigned gen) {
    __syncthreads();
    if (threadIdx.x == 0) {
        __threadfence();
        unsigned old = atomicAdd(&g_bar_cnt, 1u);
        if (old == NB - 1) {
            g_bar_cnt = 0;
            __threadfence();
            atomicExch(&g_bar_gen, gen);
        } else {
            unsigned v;
            do {
                asm volatile("ld.global.acquire.gpu.u32 %0, [%1];"
                             : "=r"(v) : "l"(&g_bar_gen));
                if (v < gen) __nanosleep(64);
            } while (v < gen);
        }
    }
    __syncthreads();
}

// ---------------- chunk loader ----------------
__device__ __forceinline__ void issue_chunk(
    uint32_t smem0, int buf, int c, int tid,
    const float* X, const float* Hs, const u64* wx, const u64* wh)
{
    // activations: 4 groups x 32k x 64b = 2048 x 16B
    #pragma unroll
    for (int q = 0; q < 8; ++q) {
        int id = tid + q * 256;
        int ag = id >> 9, kk = (id >> 4) & 31, b16 = id & 15;
        const float* ab = (ag < 2) ? X : Hs;
        const float* src = ab + (((ag & 1) * 512 + c * KC + kk) << 6) + b16 * 4;
        uint32_t dst = smem0 + OFF_ACT + (buf * 4 + ag) * ACT_GSZ + kk * ACT_ROW + b16 * 16;
        cpasync16(dst, src);
    }
    // weights: 4 groups x 32k x 16 pairs = 1024 x 16B
    #pragma unroll
    for (int q = 0; q < 4; ++q) {
        int id = tid + q * 256;
        int wg = id >> 8, kk = (id >> 3) & 31, p2 = id & 7;
        const u64* wbp = (wg < 2) ? wx : wh;
        const u64* src = wbp + (((size_t)((wg & 1) * 512 + c * KC + kk)) << 4) + p2 * 2;
        uint32_t dst = smem0 + OFF_W + (buf * 4 + wg) * W_GSZ + kk * W_ROW + p2 * 16;
        cpasync16(dst, src);
    }
    asm volatile("cp.async.commit_group;" ::: "memory");
}

// ---------------- one layer phase ----------------
__device__ __forceinline__ void lstm_phase(
    uint32_t smem0, char* smemc, int cb, int tid,
    const float* X, const float* Hs, float* HoutT,
    const u64* wx, const u64* wh, const float* bsm,
    float* Yout, int skip, float& cr0, float& cr1)
{
    int g = tid >> 6, tg = tid & 63, bgrp = tg & 15, ggrp = tg >> 4;
    int skipg = skip && (g < 2);

    u64 acc[16];
    #pragma unroll
    for (int i = 0; i < 16; ++i) acc[i] = 0ULL;

    issue_chunk(smem0, 0, 0, tid, X, Hs, wx, wh);

    for (int c = 0; c < NCH; ++c) {
        asm volatile("cp.async.wait_group 0;" ::: "memory");
        __syncthreads();
        if (c < NCH - 1) issue_chunk(smem0, (c + 1) & 1, c + 1, tid, X, Hs, wx, wh);
        if (!skipg) {
            const char* ab = smemc + OFF_ACT + ((c & 1) * 4 + g) * ACT_GSZ + bgrp * 16;
            const char* wb = smemc + OFF_W   + ((c & 1) * 4 + g) * W_GSZ  + ggrp * 32;
            #pragma unroll 8
            for (int kk = 0; kk < KC; ++kk) {
                float4 av = *(const float4*)(ab + kk * ACT_ROW);
                ulonglong2 wA = *(const ulonglong2*)(wb + kk * W_ROW);
                ulonglong2 wB = *(const ulonglong2*)(wb + kk * W_ROW + 16);
                u64 a0 = splat2(av.x), a1 = splat2(av.y);
                u64 a2 = splat2(av.z), a3 = splat2(av.w);
                acc[0]  = ffma2(a0, wA.x, acc[0]);
                acc[1]  = ffma2(a0, wA.y, acc[1]);
                acc[2]  = ffma2(a0, wB.x, acc[2]);
                acc[3]  = ffma2(a0, wB.y, acc[3]);
                acc[4]  = ffma2(a1, wA.x, acc[4]);
                acc[5]  = ffma2(a1, wA.y, acc[5]);
                acc[6]  = ffma2(a1, wB.x, acc[6]);
                acc[7]  = ffma2(a1, wB.y, acc[7]);
                acc[8]  = ffma2(a2, wA.x, acc[8]);
                acc[9]  = ffma2(a2, wA.y, acc[9]);
                acc[10] = ffma2(a2, wB.x, acc[10]);
                acc[11] = ffma2(a2, wB.y, acc[11]);
                acc[12] = ffma2(a3, wA.x, acc[12]);
                acc[13] = ffma2(a3, wA.y, acc[13]);
                acc[14] = ffma2(a3, wB.x, acc[14]);
                acc[15] = ffma2(a3, wB.y, acc[15]);
            }
        }
    }

    // store split-K partials
    u64* Gs = (u64*)(smemc + OFF_GS);
    #pragma unroll
    for (int i = 0; i < 4; ++i)
        #pragma unroll
        for (int j = 0; j < 4; ++j)
            Gs[(size_t)(g * 64 + 4 * bgrp + i) * GS_ROW + 4 * ggrp + j] = acc[4 * i + j];
    __syncthreads();

    // epilogue: combine 4 partials, gates, cell update (c in registers)
    const float* Gsf = (const float*)(smemc + OFF_GS);
    int b0 = tid >> 3, j = tid & 7, col = cb + j;
    #pragma unroll
    for (int h = 0; h < 2; ++h) {
        int b = b0 + 32 * h;
        float gi = 0, gf = 0, gg = 0, go = 0;
        #pragma unroll
        for (int g2 = 0; g2 < 4; ++g2) {
            const float* r = Gsf + (size_t)(g2 * 64 + b) * (GS_ROW * 2);
            gi += r[j]; gf += r[8 + j]; gg += r[16 + j]; go += r[24 + j];
        }
        gi += bsm[j]; gf += bsm[8 + j]; gg += bsm[16 + j]; go += bsm[24 + j];
        float cold = h ? cr1 : cr0;
        float cn = sigf(gf) * cold + sigf(gi) * tanhf_(gg);
        float hn = sigf(go) * tanhf_(cn);
        if (h) cr1 = cn; else cr0 = cn;
        HoutT[col * B_ + b] = hn;
        if (Yout) Yout[(size_t)b * H_ + col] = hn;
    }
}

// ---------------- persistent sequence kernel ----------------
__global__ void __launch_bounds__(NT, 1) lstm_seq(
    const float* __restrict__ c0in, float* __restrict__ out, int T)
{
    extern __shared__ char smemc[];
    uint32_t smem0 = (uint32_t)__cvta_generic_to_shared(smemc);
    int tid = threadIdx.x, cta = blockIdx.x, cb = cta * 8;

    float* bsm = (float*)(smemc + OFF_BIAS);
    if (tid < 96) {
        int s = tid >> 5, jj = tid & 31;
        bsm[s * 32 + jj] = g_bias[s][((jj >> 3) << 10) + cb + (jj & 7)];
    }
    int b0 = tid >> 3, j0 = tid & 7;
    float c0r0 = c0in[(size_t)b0 * H_ + cb + j0];
    float c0r1 = c0in[(size_t)(b0 + 32) * H_ + cb + j0];
    float c1r0 = c0in[(size_t)B_ * H_ + (size_t)b0 * H_ + cb + j0];
    float c1r1 = c0in[(size_t)B_ * H_ + (size_t)(b0 + 32) * H_ + cb + j0];
    __syncthreads();

    const u64* wp0x = g_Wpair + ((size_t)(0 * 128 + cta) << 14);
    const u64* wp0h = g_Wpair + ((size_t)(1 * 128 + cta) << 14);
    const u64* wp1x = g_Wpair + ((size_t)(2 * 128 + cta) << 14);
    const u64* wp1h = g_Wpair + ((size_t)(3 * 128 + cta) << 14);

    unsigned gen = 0;
    for (int t = 0; t < T; ++t) {
        int rb = t & 1, wbuf = rb ^ 1;
        lstm_phase(smem0, smemc, cb, tid,
                   g_h1T[rb], g_h0T[rb], g_h0T[wbuf],
                   wp0x, wp0h, bsm + (t ? 0 : 32),
                   nullptr, t == 0, c0r0, c0r1);
        grid_bar(++gen);
        lstm_phase(smem0, smemc, cb, tid,
                   g_h0T[wbuf], g_h1T[rb], g_h1T[wbuf],
                   wp1x, wp1h, bsm + 64,
                   out + (size_t)t * B_ * H_, 0, c1r0, c1r1);
        grid_bar(++gen);
    }
}

// ---------------- launch ----------------
extern "C" void kernel_launch(void* const* d_in, const int* in_sizes, int n_in,
                              void* d_out, int out_size) {
    const float* h0  = (const float*)d_in[0];
    const float* c0v = (const float*)d_in[1];
    const float* wih = (const float*)d_in[2];
    const float* whh = (const float*)d_in[3];
    const float* bih = (const float*)d_in[4];
    const float* bhh = (const float*)d_in[5];
    const float* ow  = (const float*)d_in[6];
    const float* ob  = (const float*)d_in[7];
    float* out = (float*)d_out;
    int T = out_size / (B_ * H_);

    prep_state<<<256, 256>>>(h0);
    prep_bias<<<128, 256>>>(wih, bih, bhh, ob);
    prep_wprime<<<dim3(32, 128), 256>>>(wih, ow);
    prep_pair<<<dim3(128, 4), 256>>>(wih, whh);

    cudaFuncSetAttribute(lstm_seq, cudaFuncAttributeMaxDynamicSharedMemorySize, SMEM_TOT);
    lstm_seq<<<NB, NT, SMEM_TOT>>>(c0v, out, T);
}